// round 1
// baseline (speedup 1.0000x reference)
#include <cuda_runtime.h>
#include <cuda_bf16.h>

// ---------------- problem constants ----------------
constexpr int Bsz  = 8;
constexpr int Lseq = 1024;
constexpr int DM   = 256;   // d_model
constexpr int DI   = 512;   // d_inner
constexpr int DS   = 16;    // d_state
constexpr int DR   = 16;    // dt_rank
constexpr int KD   = 4;     // directions
constexpr int CC   = DR + 2*DS;  // 48

// ---------------- scratch (device globals; no allocation) ----------------
__device__ float g_xssm[Bsz*Lseq*DI];   // (B,L,DI) pre-conv x
__device__ float g_z   [Bsz*Lseq*DI];   // (B,L,DI) silu(z)
__device__ float g_xcT [Bsz*Lseq*DI];   // (B,L,DI) conv+silu output
__device__ float g_P   [Bsz*KD*Lseq*CC];// (B,K,L,48) x_proj output (un-permuted)
__device__ float g_ysum[Bsz*Lseq*DI];   // (B,L,DI) scan output accumulator / normalized

__device__ __forceinline__ float siluf(float v){
    return v * (1.0f / (1.0f + __expf(-v)));
}

// ---------------- zero accumulator ----------------
__global__ void zero_ysum(){
    int i = blockIdx.x*blockDim.x + threadIdx.x;     // 4096*256 = 1M float4
    ((float4*)g_ysum)[i] = make_float4(0.f,0.f,0.f,0.f);
}

// ---------------- GEMM1: xz = x @ in_proj_w^T, split + silu(z) ----------------
// M=8192, N=1024, K=256.  A[m,k]=x, W[n,k]=in_proj_w
__global__ __launch_bounds__(256) void gemm_inproj(const float* __restrict__ A,
                                                   const float* __restrict__ W){
    constexpr int BM=128, BN=64, BK=16;
    __shared__ float As[BK][BM];
    __shared__ float Bs[BK][BN];
    const int m0 = blockIdx.x * BM;
    const int n0 = blockIdx.y * BN;
    const int tid = threadIdx.x;
    const int tx = tid & 15;   // n-tile
    const int ty = tid >> 4;   // m-tile
    const int arow = tid >> 1, acol = (tid & 1) * 8;
    const int brow = tid >> 2, bcol = (tid & 3) * 4;

    float acc[8][4] = {};
    for (int kt = 0; kt < 256; kt += BK){
        float4 av0 = *(const float4*)&A[(size_t)(m0+arow)*256 + kt + acol];
        float4 av1 = *(const float4*)&A[(size_t)(m0+arow)*256 + kt + acol + 4];
        float4 bv  = *(const float4*)&W[(size_t)(n0+brow)*256 + kt + bcol];
        __syncthreads();
        As[acol+0][arow]=av0.x; As[acol+1][arow]=av0.y; As[acol+2][arow]=av0.z; As[acol+3][arow]=av0.w;
        As[acol+4][arow]=av1.x; As[acol+5][arow]=av1.y; As[acol+6][arow]=av1.z; As[acol+7][arow]=av1.w;
        Bs[bcol+0][brow]=bv.x;  Bs[bcol+1][brow]=bv.y;  Bs[bcol+2][brow]=bv.z;  Bs[bcol+3][brow]=bv.w;
        __syncthreads();
        #pragma unroll
        for (int k=0;k<BK;k++){
            float a[8], bb[4];
            *(float4*)&a[0] = *(const float4*)&As[k][ty*8];
            *(float4*)&a[4] = *(const float4*)&As[k][ty*8+4];
            *(float4*)&bb[0]= *(const float4*)&Bs[k][tx*4];
            #pragma unroll
            for (int i=0;i<8;i++)
                #pragma unroll
                for (int j=0;j<4;j++)
                    acc[i][j] = fmaf(a[i], bb[j], acc[i][j]);
        }
    }
    #pragma unroll
    for (int i=0;i<8;i++){
        int m = m0 + ty*8 + i;
        #pragma unroll
        for (int j=0;j<4;j++){
            int n = n0 + tx*4 + j;
            float v = acc[i][j];
            if (n < DI) g_xssm[(size_t)m*DI + n] = v;
            else        g_z  [(size_t)m*DI + n - DI] = siluf(v);
        }
    }
}

// ---------------- conv1d depthwise (k=4, pad 1/2) + silu; (B,L,DI) -> (B,L,DI) ----------------
__global__ __launch_bounds__(512) void conv_silu(const float* __restrict__ cw,
                                                 const float* __restrict__ cb){
    const int d  = threadIdx.x;           // 0..511
    const int b  = blockIdx.y;
    const int l0 = blockIdx.x * 64;
    const float w0=cw[d*4+0], w1=cw[d*4+1], w2=cw[d*4+2], w3=cw[d*4+3], bias=cb[d];
    const float* src = g_xssm + (size_t)b*Lseq*DI + d;
    float xm1 = (l0>0)   ? src[(size_t)(l0-1)*DI] : 0.f;
    float x0  =            src[(size_t)(l0  )*DI];
    float xp1 =            src[(size_t)(l0+1)*DI];
    #pragma unroll 4
    for (int l=l0; l<l0+64; l++){
        float xp2 = (l+2 < Lseq) ? src[(size_t)(l+2)*DI] : 0.f;
        float v = w0*xm1 + w1*x0 + w2*xp1 + w3*xp2 + bias;
        g_xcT[((size_t)b*Lseq + l)*DI + d] = siluf(v);
        xm1=x0; x0=xp1; xp1=xp2;
    }
}

// ---------------- GEMM2: P[b,k,lam,c] = sum_d xcT[b,lam,d] * x_proj_w[k,c,d] ----------------
// M=8192 (b,lam), N=48, K=512; blockIdx.y = direction k
__global__ __launch_bounds__(256) void gemm_xdbl(const float* __restrict__ xproj_w){
    constexpr int BM=128, BN=48, BK=16;
    __shared__ float As[BK][BM];
    __shared__ float Bs[BK][BN];
    const int m0 = blockIdx.x * BM;
    const int kd = blockIdx.y;
    const float* A = g_xcT;
    const float* W = xproj_w + (size_t)kd*CC*DI;
    const int tid = threadIdx.x;
    const int tx = tid & 15;   // n-tile: c = tx*3..tx*3+2
    const int ty = tid >> 4;   // m-tile
    const int arow = tid >> 1, acol = (tid & 1) * 8;

    float acc[8][3] = {};
    for (int kt = 0; kt < DI; kt += BK){
        float4 av0 = *(const float4*)&A[(size_t)(m0+arow)*DI + kt + acol];
        float4 av1 = *(const float4*)&A[(size_t)(m0+arow)*DI + kt + acol + 4];
        float bvs[3]; int bns[3], bks[3];
        #pragma unroll
        for (int t=0;t<3;t++){
            int lin = tid*3 + t;
            bns[t] = lin >> 4; bks[t] = lin & 15;
            bvs[t] = W[(size_t)bns[t]*DI + kt + bks[t]];
        }
        __syncthreads();
        As[acol+0][arow]=av0.x; As[acol+1][arow]=av0.y; As[acol+2][arow]=av0.z; As[acol+3][arow]=av0.w;
        As[acol+4][arow]=av1.x; As[acol+5][arow]=av1.y; As[acol+6][arow]=av1.z; As[acol+7][arow]=av1.w;
        #pragma unroll
        for (int t=0;t<3;t++) Bs[bks[t]][bns[t]] = bvs[t];
        __syncthreads();
        #pragma unroll
        for (int k=0;k<BK;k++){
            float a[8], bb[3];
            *(float4*)&a[0] = *(const float4*)&As[k][ty*8];
            *(float4*)&a[4] = *(const float4*)&As[k][ty*8+4];
            bb[0]=Bs[k][tx*3]; bb[1]=Bs[k][tx*3+1]; bb[2]=Bs[k][tx*3+2];
            #pragma unroll
            for (int i=0;i<8;i++)
                #pragma unroll
                for (int j=0;j<3;j++)
                    acc[i][j] = fmaf(a[i], bb[j], acc[i][j]);
        }
    }
    #pragma unroll
    for (int i=0;i<8;i++){
        int m = m0 + ty*8 + i;
        int b = m >> 10, lam = m & 1023;
        float* dst = &g_P[(((size_t)b*KD + kd)*Lseq + lam)*CC];
        #pragma unroll
        for (int j=0;j<3;j++) dst[tx*3+j] = acc[i][j];
    }
}

// ---------------- scan: fused dt_proj + softplus + selective scan + D*u, scatter-add ----------------
__device__ __forceinline__ int lam_of(int l, int k){
    switch(k){
        case 0:  return l;
        case 1:  return Lseq-1-l;
        case 2:  return (l < Lseq/2) ? 2*l     : 2*(l-Lseq/2)+1;
        default: return (l < Lseq/2) ? 2*l + 1 : 2*(l-Lseq/2);
    }
}

__global__ __launch_bounds__(128) void scan_kernel(const float* __restrict__ dt_proj_w,
                                                   const float* __restrict__ dt_bias,
                                                   const float* __restrict__ A_logs,
                                                   const float* __restrict__ Ds){
    const int tid = threadIdx.x;
    const int d   = blockIdx.x*128 + tid;
    const int kd  = blockIdx.y;
    const int b   = blockIdx.z;

    float dtw[16], a[16], h[16];
    {
        const float4* p = (const float4*)&dt_proj_w[((size_t)kd*DI + d)*DR];
        #pragma unroll
        for (int q=0;q<4;q++){ float4 v=p[q]; dtw[4*q]=v.x; dtw[4*q+1]=v.y; dtw[4*q+2]=v.z; dtw[4*q+3]=v.w; }
        const float* al = &A_logs[((size_t)kd*DI + d)*DS];
        #pragma unroll
        for (int n=0;n<16;n++){ a[n] = -__expf(al[n]); h[n] = 0.f; }
    }
    const float bias = dt_bias[kd*DI + d];
    const float Dd   = Ds[kd*DI + d];

    __shared__ float sP[64*CC];   // 64 steps staged
    const float* Pbase = g_P   + ((size_t)b*KD + kd)*Lseq*CC;
    const float* Ubase = g_xcT + (size_t)b*Lseq*DI + d;
    float*       Ybase = g_ysum+ (size_t)b*Lseq*DI + d;

    for (int l0 = 0; l0 < Lseq; l0 += 64){
        __syncthreads();
        for (int s = tid; s < 64*CC; s += 128){
            int st = s / CC, c = s - st*CC;
            int lam = lam_of(l0 + st, kd);
            sP[st*CC + c] = Pbase[(size_t)lam*CC + c];
        }
        __syncthreads();
        for (int st = 0; st < 64; st++){
            const int lam = lam_of(l0 + st, kd);
            const float u = Ubase[(size_t)lam*DI];
            const float* row = &sP[st*CC];
            float x = bias;
            #pragma unroll
            for (int r=0;r<16;r++) x = fmaf(dtw[r], row[r], x);
            // softplus (stable)
            float e = __expf(-fabsf(x));
            float delta = fmaxf(x, 0.f) + __logf(1.f + e);
            float du = delta * u;
            float y = 0.f;
            #pragma unroll
            for (int n=0;n<16;n++){
                float dA = __expf(delta * a[n]);
                h[n] = fmaf(h[n], dA, du * row[16+n]);
                y = fmaf(h[n], row[32+n], y);
            }
            atomicAdd(&Ybase[(size_t)lam*DI], y + Dd*u);
        }
    }
}

// ---------------- layernorm(D_INNER) * ln_g + ln_b, gated by silu(z); in place ----------------
__global__ __launch_bounds__(128) void norm_kernel(const float* __restrict__ ln_g,
                                                   const float* __restrict__ ln_b){
    const int row = blockIdx.x;          // (b,l) row, 0..8191
    const int tid = threadIdx.x;
    float* y = g_ysum + (size_t)row*DI;
    const float* z = g_z + (size_t)row*DI;

    float4 v = ((const float4*)y)[tid];
    float s  = v.x+v.y+v.z+v.w;
    float sq = v.x*v.x + v.y*v.y + v.z*v.z + v.w*v.w;
    #pragma unroll
    for (int o=16;o>0;o>>=1){
        s  += __shfl_xor_sync(0xffffffffu, s,  o);
        sq += __shfl_xor_sync(0xffffffffu, sq, o);
    }
    __shared__ float ss[4], sqq[4];
    const int wid = tid >> 5, lane = tid & 31;
    if (lane==0){ ss[wid]=s; sqq[wid]=sq; }
    __syncthreads();
    s  = ss[0]+ss[1]+ss[2]+ss[3];
    sq = sqq[0]+sqq[1]+sqq[2]+sqq[3];
    const float mu  = s * (1.f/512.f);
    const float var = sq * (1.f/512.f) - mu*mu;
    const float rs  = rsqrtf(var + 1e-5f);

    float4 g4 = ((const float4*)ln_g)[tid];
    float4 b4 = ((const float4*)ln_b)[tid];
    float4 z4 = ((const float4*)z)[tid];
    v.x = ((v.x-mu)*rs*g4.x + b4.x) * z4.x;
    v.y = ((v.y-mu)*rs*g4.y + b4.y) * z4.y;
    v.z = ((v.z-mu)*rs*g4.z + b4.z) * z4.z;
    v.w = ((v.w-mu)*rs*g4.w + b4.w) * z4.w;
    ((float4*)y)[tid] = v;
}

// ---------------- GEMM3: out = yn @ out_proj_w^T ; M=8192, N=256, K=512 ----------------
__global__ __launch_bounds__(256) void gemm_out(const float* __restrict__ W,
                                                float* __restrict__ out){
    constexpr int BM=128, BN=64, BK=16;
    __shared__ float As[BK][BM];
    __shared__ float Bs[BK][BN];
    const int m0 = blockIdx.x * BM;
    const int n0 = blockIdx.y * BN;
    const float* A = g_ysum;
    const int tid = threadIdx.x;
    const int tx = tid & 15, ty = tid >> 4;
    const int arow = tid >> 1, acol = (tid & 1) * 8;
    const int brow = tid >> 2, bcol = (tid & 3) * 4;

    float acc[8][4] = {};
    for (int kt = 0; kt < DI; kt += BK){
        float4 av0 = *(const float4*)&A[(size_t)(m0+arow)*DI + kt + acol];
        float4 av1 = *(const float4*)&A[(size_t)(m0+arow)*DI + kt + acol + 4];
        float4 bv  = *(const float4*)&W[(size_t)(n0+brow)*DI + kt + bcol];
        __syncthreads();
        As[acol+0][arow]=av0.x; As[acol+1][arow]=av0.y; As[acol+2][arow]=av0.z; As[acol+3][arow]=av0.w;
        As[acol+4][arow]=av1.x; As[acol+5][arow]=av1.y; As[acol+6][arow]=av1.z; As[acol+7][arow]=av1.w;
        Bs[bcol+0][brow]=bv.x;  Bs[bcol+1][brow]=bv.y;  Bs[bcol+2][brow]=bv.z;  Bs[bcol+3][brow]=bv.w;
        __syncthreads();
        #pragma unroll
        for (int k=0;k<BK;k++){
            float a[8], bb[4];
            *(float4*)&a[0] = *(const float4*)&As[k][ty*8];
            *(float4*)&a[4] = *(const float4*)&As[k][ty*8+4];
            *(float4*)&bb[0]= *(const float4*)&Bs[k][tx*4];
            #pragma unroll
            for (int i=0;i<8;i++)
                #pragma unroll
                for (int j=0;j<4;j++)
                    acc[i][j] = fmaf(a[i], bb[j], acc[i][j]);
        }
    }
    #pragma unroll
    for (int i=0;i<8;i++){
        int m = m0 + ty*8 + i;
        #pragma unroll
        for (int j=0;j<4;j++){
            int n = n0 + tx*4 + j;
            out[(size_t)m*DM + n] = acc[i][j];
        }
    }
}

// ---------------- launch ----------------
extern "C" void kernel_launch(void* const* d_in, const int* in_sizes, int n_in,
                              void* d_out, int out_size){
    const float* x          = (const float*)d_in[0];
    const float* in_proj_w  = (const float*)d_in[1];
    const float* conv_w     = (const float*)d_in[2];
    const float* conv_b     = (const float*)d_in[3];
    const float* x_proj_w   = (const float*)d_in[4];
    const float* dt_proj_w  = (const float*)d_in[5];
    const float* dt_bias    = (const float*)d_in[6];
    const float* A_logs     = (const float*)d_in[7];
    const float* Ds         = (const float*)d_in[8];
    const float* ln_g       = (const float*)d_in[9];
    const float* ln_b       = (const float*)d_in[10];
    const float* out_proj_w = (const float*)d_in[11];
    float* out = (float*)d_out;

    zero_ysum  <<<4096, 256>>>();
    gemm_inproj<<<dim3(64,16), 256>>>(x, in_proj_w);
    conv_silu  <<<dim3(16, 8), 512>>>(conv_w, conv_b);
    gemm_xdbl  <<<dim3(64, 4), 256>>>(x_proj_w);
    scan_kernel<<<dim3(4, 4, 8), 128>>>(dt_proj_w, dt_bias, A_logs, Ds);
    norm_kernel<<<8192, 128>>>(ln_g, ln_b);
    gemm_out   <<<dim3(64, 4), 256>>>(out_proj_w, out);
}

// round 2
// speedup vs baseline: 1.2930x; 1.2930x over previous
#include <cuda_runtime.h>
#include <cuda_bf16.h>

// ---------------- problem constants ----------------
constexpr int Bsz  = 8;
constexpr int Lseq = 1024;
constexpr int DM   = 256;   // d_model
constexpr int DI   = 512;   // d_inner
constexpr int DS   = 16;    // d_state
constexpr int DR   = 16;    // dt_rank
constexpr int KD   = 4;     // directions
constexpr int CC   = DR + 2*DS;  // 48

// ---------------- scratch (device globals; no allocation) ----------------
__device__ float g_xssm[Bsz*Lseq*DI];   // (B,L,DI) pre-conv x
__device__ float g_z   [Bsz*Lseq*DI];   // (B,L,DI) silu(z)
__device__ float g_xcT [Bsz*Lseq*DI];   // (B,L,DI) conv+silu output
__device__ float g_P   [Bsz*KD*Lseq*CC];// (B,K,L,48) x_proj output (un-permuted)
__device__ float g_ysum[Bsz*Lseq*DI];   // (B,L,DI) scan output accumulator / normalized

__device__ __forceinline__ float siluf(float v){
    return v * (1.0f / (1.0f + __expf(-v)));
}

__device__ __forceinline__ unsigned f2tf(float f){
    unsigned u; asm("cvt.rna.tf32.f32 %0, %1;" : "=r"(u) : "f"(f)); return u;
}

__device__ __forceinline__ void mma_tf32(float (&c)[4], const unsigned (&a)[4], const unsigned (&b)[2]){
    asm volatile(
        "mma.sync.aligned.m16n8k8.row.col.f32.tf32.tf32.f32 "
        "{%0,%1,%2,%3}, {%4,%5,%6,%7}, {%8,%9}, {%0,%1,%2,%3};\n"
        : "+f"(c[0]), "+f"(c[1]), "+f"(c[2]), "+f"(c[3])
        : "r"(a[0]), "r"(a[1]), "r"(a[2]), "r"(a[3]), "r"(b[0]), "r"(b[1]));
}

// ---------------- zero accumulator ----------------
__global__ void zero_ysum(){
    int i = blockIdx.x*blockDim.x + threadIdx.x;
    ((float4*)g_ysum)[i] = make_float4(0.f,0.f,0.f,0.f);
}

// ---------------- tf32 tensor-core GEMM: C = A @ W^T ----------------
// INPROJ=true : A=x (Mx256), W=in_proj_w (1024x256); split -> g_xssm / silu -> g_z
// INPROJ=false: A=g_ysum (Mx512), W=out_proj_w (256x512); write outp (Mx256)
template<int KDIM, bool INPROJ>
__global__ __launch_bounds__(256) void gemm_tc(const float* __restrict__ Ain,
                                               const float* __restrict__ W,
                                               float* __restrict__ outp){
    constexpr int BM=128, BN=64, BK=16;
    __shared__ float As[BM][20];
    __shared__ float Ws[BN][20];
    const float* A = INPROJ ? Ain : (const float*)g_ysum;
    const int m0 = blockIdx.x*BM, n0 = blockIdx.y*BN;
    const int tid = threadIdx.x;
    const int wid = tid>>5, lane = tid&31;
    const int wm = wid & 3, wn = wid >> 2;      // 4 x 2 warp grid, warp tile 32x32
    const int g = lane>>2, tg = lane&3;

    const int alr = tid>>1, alc = (tid&1)*8;
    const int wlr = tid>>2, wlc = (tid&3)*4;

    float c[2][4][4] = {};

    for (int kt=0; kt<KDIM; kt+=BK){
        float4 av0 = *(const float4*)&A[(size_t)(m0+alr)*KDIM + kt+alc];
        float4 av1 = *(const float4*)&A[(size_t)(m0+alr)*KDIM + kt+alc+4];
        float4 wv  = *(const float4*)&W[(size_t)(n0+wlr)*KDIM + kt+wlc];
        __syncthreads();
        *(float4*)&As[alr][alc]   = av0;
        *(float4*)&As[alr][alc+4] = av1;
        *(float4*)&Ws[wlr][wlc]   = wv;
        __syncthreads();
        #pragma unroll
        for (int ks=0; ks<BK; ks+=8){
            unsigned a[2][4], b[4][2];
            #pragma unroll
            for (int mf=0;mf<2;mf++){
                int r = wm*32 + mf*16;
                a[mf][0]=f2tf(As[r+g  ][ks+tg  ]);
                a[mf][1]=f2tf(As[r+g+8][ks+tg  ]);
                a[mf][2]=f2tf(As[r+g  ][ks+tg+4]);
                a[mf][3]=f2tf(As[r+g+8][ks+tg+4]);
            }
            #pragma unroll
            for (int nf=0;nf<4;nf++){
                int n = wn*32 + nf*8;
                b[nf][0]=f2tf(Ws[n+g][ks+tg  ]);
                b[nf][1]=f2tf(Ws[n+g][ks+tg+4]);
            }
            #pragma unroll
            for (int mf=0;mf<2;mf++)
                #pragma unroll
                for (int nf=0;nf<4;nf++)
                    mma_tf32(c[mf][nf], a[mf], b[nf]);
        }
    }
    // epilogue
    #pragma unroll
    for (int mf=0;mf<2;mf++){
        #pragma unroll
        for (int nf=0;nf<4;nf++){
            int row = m0 + wm*32 + mf*16 + g;
            int col = n0 + wn*32 + nf*8 + 2*tg;
            #pragma unroll
            for (int hh=0; hh<2; hh++){
                int r = row + hh*8;
                float v0 = c[mf][nf][hh*2+0];
                float v1 = c[mf][nf][hh*2+1];
                if (INPROJ){
                    if (col < DI){
                        g_xssm[(size_t)r*DI + col]   = v0;
                        g_xssm[(size_t)r*DI + col+1] = v1;
                    } else {
                        g_z[(size_t)r*DI + col-DI]   = siluf(v0);
                        g_z[(size_t)r*DI + col-DI+1] = siluf(v1);
                    }
                } else {
                    outp[(size_t)r*DM + col]   = v0;
                    outp[(size_t)r*DM + col+1] = v1;
                }
            }
        }
    }
}

// ---------------- conv1d depthwise (k=4, pad 1/2) + silu ----------------
__global__ __launch_bounds__(512) void conv_silu(const float* __restrict__ cw,
                                                 const float* __restrict__ cb){
    const int d  = threadIdx.x;
    const int b  = blockIdx.y;
    const int l0 = blockIdx.x * 64;
    const float w0=cw[d*4+0], w1=cw[d*4+1], w2=cw[d*4+2], w3=cw[d*4+3], bias=cb[d];
    const float* src = g_xssm + (size_t)b*Lseq*DI + d;
    float xm1 = (l0>0)   ? src[(size_t)(l0-1)*DI] : 0.f;
    float x0  =            src[(size_t)(l0  )*DI];
    float xp1 =            src[(size_t)(l0+1)*DI];
    #pragma unroll 4
    for (int l=l0; l<l0+64; l++){
        float xp2 = (l+2 < Lseq) ? src[(size_t)(l+2)*DI] : 0.f;
        float v = w0*xm1 + w1*x0 + w2*xp1 + w3*xp2 + bias;
        g_xcT[((size_t)b*Lseq + l)*DI + d] = siluf(v);
        xm1=x0; x0=xp1; xp1=xp2;
    }
}

// ---------------- GEMM2: P[b,k,lam,c] = sum_d xcT[b,lam,d] * x_proj_w[k,c,d] ----------------
__global__ __launch_bounds__(256) void gemm_xdbl(const float* __restrict__ xproj_w){
    constexpr int BM=128, BK=16;
    __shared__ float As[BK][BM];
    __shared__ float Bs[BK][48];
    const int m0 = blockIdx.x * BM;
    const int kd = blockIdx.y;
    const float* A = g_xcT;
    const float* W = xproj_w + (size_t)kd*CC*DI;
    const int tid = threadIdx.x;
    const int tx = tid & 15;
    const int ty = tid >> 4;
    const int arow = tid >> 1, acol = (tid & 1) * 8;

    float acc[8][3] = {};
    for (int kt = 0; kt < DI; kt += BK){
        float4 av0 = *(const float4*)&A[(size_t)(m0+arow)*DI + kt + acol];
        float4 av1 = *(const float4*)&A[(size_t)(m0+arow)*DI + kt + acol + 4];
        float bvs[3]; int bns[3], bks[3];
        #pragma unroll
        for (int t=0;t<3;t++){
            int lin = tid*3 + t;
            bns[t] = lin >> 4; bks[t] = lin & 15;
            bvs[t] = W[(size_t)bns[t]*DI + kt + bks[t]];
        }
        __syncthreads();
        As[acol+0][arow]=av0.x; As[acol+1][arow]=av0.y; As[acol+2][arow]=av0.z; As[acol+3][arow]=av0.w;
        As[acol+4][arow]=av1.x; As[acol+5][arow]=av1.y; As[acol+6][arow]=av1.z; As[acol+7][arow]=av1.w;
        #pragma unroll
        for (int t=0;t<3;t++) Bs[bks[t]][bns[t]] = bvs[t];
        __syncthreads();
        #pragma unroll
        for (int k=0;k<BK;k++){
            float a[8], bb[3];
            *(float4*)&a[0] = *(const float4*)&As[k][ty*8];
            *(float4*)&a[4] = *(const float4*)&As[k][ty*8+4];
            bb[0]=Bs[k][tx*3]; bb[1]=Bs[k][tx*3+1]; bb[2]=Bs[k][tx*3+2];
            #pragma unroll
            for (int i=0;i<8;i++)
                #pragma unroll
                for (int j=0;j<3;j++)
                    acc[i][j] = fmaf(a[i], bb[j], acc[i][j]);
        }
    }
    #pragma unroll
    for (int i=0;i<8;i++){
        int m = m0 + ty*8 + i;
        int b = m >> 10, lam = m & 1023;
        float* dst = &g_P[(((size_t)b*KD + kd)*Lseq + lam)*CC];
        #pragma unroll
        for (int j=0;j<3;j++) dst[tx*3+j] = acc[i][j];
    }
}

// ---------------- scan helpers ----------------
__device__ __forceinline__ int lam_of(int l, int k){
    switch(k){
        case 0:  return l;
        case 1:  return Lseq-1-l;
        case 2:  return (l < Lseq/2) ? 2*l     : 2*(l-Lseq/2)+1;
        default: return (l < Lseq/2) ? 2*l + 1 : 2*(l-Lseq/2);
    }
}

// CHAIN: dA_n = e^(n+1) via multiply tree (1 MUFU/step); else generic exp per state.
template<bool CHAIN>
__device__ __forceinline__ void scan_loop(float* sP,
                                          const float* __restrict__ Pbase,
                                          const float* __restrict__ Ubase,
                                          float*       __restrict__ Ybase,
                                          const float (&dtw)[16], const float (&a)[16],
                                          float a0, float bias, float Dd,
                                          int kd, int tid){
    float h[16];
    #pragma unroll
    for (int n=0;n<16;n++) h[n]=0.f;

    for (int l0 = 0; l0 < Lseq; l0 += 64){
        __syncthreads();
        for (int s = tid; s < 64*CC; s += 128){
            int st = s / CC, c = s - st*CC;
            int lam = lam_of(l0 + st, kd);
            sP[st*CC + c] = Pbase[(size_t)lam*CC + c];
        }
        __syncthreads();
        for (int st = 0; st < 64; st++){
            const int lam = lam_of(l0 + st, kd);
            const float u = Ubase[(size_t)lam*DI];
            const float* row = &sP[st*CC];
            float x = bias;
            #pragma unroll
            for (int r=0;r<16;r++) x = fmaf(dtw[r], row[r], x);
            float e0 = __expf(-fabsf(x));
            float delta = fmaxf(x, 0.f) + __logf(1.f + e0);
            float du = delta * u;
            float y = 0.f;
            if (CHAIN){
                float e1 = __expf(delta * a0);
                float e2 = e1*e1, e4 = e2*e2, e8 = e4*e4;
                float pw[16];
                pw[0]=e1;        pw[1]=e2;        pw[2]=e2*e1;     pw[3]=e4;
                pw[4]=e4*e1;     pw[5]=e4*e2;     pw[6]=pw[2]*e4;  pw[7]=e8;
                pw[8]=e8*e1;     pw[9]=e8*e2;     pw[10]=pw[2]*e8; pw[11]=e8*e4;
                pw[12]=pw[4]*e8; pw[13]=pw[5]*e8; pw[14]=pw[6]*e8; pw[15]=e8*e8;
                #pragma unroll
                for (int n=0;n<16;n++){
                    h[n] = fmaf(h[n], pw[n], du * row[16+n]);
                    y = fmaf(h[n], row[32+n], y);
                }
            } else {
                #pragma unroll
                for (int n=0;n<16;n++){
                    float dA = __expf(delta * a[n]);
                    h[n] = fmaf(h[n], dA, du * row[16+n]);
                    y = fmaf(h[n], row[32+n], y);
                }
            }
            atomicAdd(&Ybase[(size_t)lam*DI], y + Dd*u);
        }
    }
}

__global__ __launch_bounds__(128) void scan_kernel(const float* __restrict__ dt_proj_w,
                                                   const float* __restrict__ dt_bias,
                                                   const float* __restrict__ A_logs,
                                                   const float* __restrict__ Ds){
    const int tid = threadIdx.x;
    const int d   = blockIdx.x*128 + tid;
    const int kd  = blockIdx.y;
    const int b   = blockIdx.z;

    float dtw[16], a[16];
    {
        const float4* p = (const float4*)&dt_proj_w[((size_t)kd*DI + d)*DR];
        #pragma unroll
        for (int q=0;q<4;q++){ float4 v=p[q]; dtw[4*q]=v.x; dtw[4*q+1]=v.y; dtw[4*q+2]=v.z; dtw[4*q+3]=v.w; }
        const float* al = &A_logs[((size_t)kd*DI + d)*DS];
        #pragma unroll
        for (int n=0;n<16;n++) a[n] = -__expf(al[n]);
    }
    const float a0   = a[0];
    const float bias = dt_bias[kd*DI + d];
    const float Dd   = Ds[kd*DI + d];

    // runtime structure check: a[n] == (n+1)*a0  (=> exp chain valid)
    int chain = 1;
    #pragma unroll
    for (int n=0;n<16;n++){
        float expect = a0 * (float)(n+1);
        if (fabsf(a[n]-expect) > 1e-4f*fabsf(expect) + 1e-30f) chain = 0;
    }
    chain = __syncthreads_and(chain);   // block-uniform decision

    __shared__ float sP[64*CC];
    const float* Pbase = g_P   + ((size_t)b*KD + kd)*Lseq*CC;
    const float* Ubase = g_xcT + (size_t)b*Lseq*DI + d;
    float*       Ybase = g_ysum+ (size_t)b*Lseq*DI + d;

    if (chain) scan_loop<true >(sP, Pbase, Ubase, Ybase, dtw, a, a0, bias, Dd, kd, tid);
    else       scan_loop<false>(sP, Pbase, Ubase, Ybase, dtw, a, a0, bias, Dd, kd, tid);
}

// ---------------- layernorm * ln_g + ln_b, gated by silu(z); in place ----------------
__global__ __launch_bounds__(128) void norm_kernel(const float* __restrict__ ln_g,
                                                   const float* __restrict__ ln_b){
    const int row = blockIdx.x;
    const int tid = threadIdx.x;
    float* y = g_ysum + (size_t)row*DI;
    const float* z = g_z + (size_t)row*DI;

    float4 v = ((const float4*)y)[tid];
    float s  = v.x+v.y+v.z+v.w;
    float sq = v.x*v.x + v.y*v.y + v.z*v.z + v.w*v.w;
    #pragma unroll
    for (int o=16;o>0;o>>=1){
        s  += __shfl_xor_sync(0xffffffffu, s,  o);
        sq += __shfl_xor_sync(0xffffffffu, sq, o);
    }
    __shared__ float ss[4], sqq[4];
    const int wid = tid >> 5, lane = tid & 31;
    if (lane==0){ ss[wid]=s; sqq[wid]=sq; }
    __syncthreads();
    s  = ss[0]+ss[1]+ss[2]+ss[3];
    sq = sqq[0]+sqq[1]+sqq[2]+sqq[3];
    const float mu  = s * (1.f/512.f);
    const float var = sq * (1.f/512.f) - mu*mu;
    const float rs  = rsqrtf(var + 1e-5f);

    float4 g4 = ((const float4*)ln_g)[tid];
    float4 b4 = ((const float4*)ln_b)[tid];
    float4 z4 = ((const float4*)z)[tid];
    v.x = ((v.x-mu)*rs*g4.x + b4.x) * z4.x;
    v.y = ((v.y-mu)*rs*g4.y + b4.y) * z4.y;
    v.z = ((v.z-mu)*rs*g4.z + b4.z) * z4.z;
    v.w = ((v.w-mu)*rs*g4.w + b4.w) * z4.w;
    ((float4*)y)[tid] = v;
}

// ---------------- launch ----------------
extern "C" void kernel_launch(void* const* d_in, const int* in_sizes, int n_in,
                              void* d_out, int out_size){
    const float* x          = (const float*)d_in[0];
    const float* in_proj_w  = (const float*)d_in[1];
    const float* conv_w     = (const float*)d_in[2];
    const float* conv_b     = (const float*)d_in[3];
    const float* x_proj_w   = (const float*)d_in[4];
    const float* dt_proj_w  = (const float*)d_in[5];
    const float* dt_bias    = (const float*)d_in[6];
    const float* A_logs     = (const float*)d_in[7];
    const float* Ds         = (const float*)d_in[8];
    const float* ln_g       = (const float*)d_in[9];
    const float* ln_b       = (const float*)d_in[10];
    const float* out_proj_w = (const float*)d_in[11];
    float* out = (float*)d_out;

    zero_ysum          <<<4096, 256>>>();
    gemm_tc<256,true>  <<<dim3(64,16), 256>>>(x, in_proj_w, nullptr);
    conv_silu          <<<dim3(16, 8), 512>>>(conv_w, conv_b);
    gemm_xdbl          <<<dim3(64, 4), 256>>>(x_proj_w);
    scan_kernel        <<<dim3(4, 4, 8), 128>>>(dt_proj_w, dt_bias, A_logs, Ds);
    norm_kernel        <<<8192, 128>>>(ln_g, ln_b);
    gemm_tc<512,false> <<<dim3(64, 4), 256>>>(nullptr, out_proj_w, out);
}

// round 3
// speedup vs baseline: 1.7652x; 1.3652x over previous
#include <cuda_runtime.h>
#include <cuda_bf16.h>

// ---------------- problem constants ----------------
constexpr int Bsz  = 8;
constexpr int Lseq = 1024;
constexpr int DM   = 256;   // d_model
constexpr int DI   = 512;   // d_inner
constexpr int DS   = 16;    // d_state
constexpr int DR   = 16;    // dt_rank
constexpr int KD   = 4;     // directions
constexpr int CC   = DR + 2*DS;  // 48
constexpr int NCH  = 16;    // scan chunks
constexpr int LC   = Lseq/NCH;   // 64 steps per chunk

// ---------------- scratch (device globals; no allocation) ----------------
__device__ float g_xssm[Bsz*Lseq*DI];    // (B,L,DI) pre-conv x
__device__ float g_z   [Bsz*Lseq*DI];    // (B,L,DI) silu(z)
__device__ float g_xcT [Bsz*Lseq*DI];    // (B,L,DI) conv+silu output
__device__ float g_P   [Bsz*Lseq*KD*CC]; // (B,L,192) x_proj output (un-permuted, all dirs)
__device__ float g_ysum[Bsz*Lseq*DI];    // (B,L,DI) scan accumulator / normalized
__device__ float g_hout[Bsz*KD*NCH*DI*DS]; // chunk-local final states
__device__ float g_hin [Bsz*KD*NCH*DI*DS]; // chunk initial states (after combine)
__device__ float g_S   [Bsz*KD*NCH*DI];    // chunk delta sums

__device__ __forceinline__ float siluf(float v){
    return v * (1.0f / (1.0f + __expf(-v)));
}

__device__ __forceinline__ unsigned f2tf(float f){
    unsigned u; asm("cvt.rna.tf32.f32 %0, %1;" : "=r"(u) : "f"(f)); return u;
}

__device__ __forceinline__ void mma_tf32(float (&c)[4], const unsigned (&a)[4], const unsigned (&b)[2]){
    asm volatile(
        "mma.sync.aligned.m16n8k8.row.col.f32.tf32.tf32.f32 "
        "{%0,%1,%2,%3}, {%4,%5,%6,%7}, {%8,%9}, {%0,%1,%2,%3};\n"
        : "+f"(c[0]), "+f"(c[1]), "+f"(c[2]), "+f"(c[3])
        : "r"(a[0]), "r"(a[1]), "r"(a[2]), "r"(a[3]), "r"(b[0]), "r"(b[1]));
}

// ---------------- zero accumulator ----------------
__global__ void zero_ysum(){
    int i = blockIdx.x*blockDim.x + threadIdx.x;
    ((float4*)g_ysum)[i] = make_float4(0.f,0.f,0.f,0.f);
}

// ---------------- tf32 tensor-core GEMM: C = A @ W^T ----------------
// MODE 0: A=x (Mx256), W=in_proj_w (1024x256); split -> g_xssm / silu -> g_z
// MODE 1: A=g_ysum (Mx512), W=out_proj_w (256x512); write outp (Mx256)
// MODE 2: A=g_xcT (Mx512), W=x_proj_w as (192x512); write g_P (Mx192)
template<int KDIM, int MODE>
__global__ __launch_bounds__(256) void gemm_tc(const float* __restrict__ Ain,
                                               const float* __restrict__ W,
                                               float* __restrict__ outp){
    constexpr int BM=128, BN=64, BK=16;
    __shared__ float As[BM][20];
    __shared__ float Ws[BN][20];
    const float* A = (MODE==0) ? Ain : (MODE==1 ? (const float*)g_ysum : (const float*)g_xcT);
    const int m0 = blockIdx.x*BM, n0 = blockIdx.y*BN;
    const int tid = threadIdx.x;
    const int wid = tid>>5, lane = tid&31;
    const int wm = wid & 3, wn = wid >> 2;      // 4 x 2 warp grid, warp tile 32x32
    const int g = lane>>2, tg = lane&3;

    const int alr = tid>>1, alc = (tid&1)*8;
    const int wlr = tid>>2, wlc = (tid&3)*4;

    float c[2][4][4] = {};

    for (int kt=0; kt<KDIM; kt+=BK){
        float4 av0 = *(const float4*)&A[(size_t)(m0+alr)*KDIM + kt+alc];
        float4 av1 = *(const float4*)&A[(size_t)(m0+alr)*KDIM + kt+alc+4];
        float4 wv  = *(const float4*)&W[(size_t)(n0+wlr)*KDIM + kt+wlc];
        __syncthreads();
        *(float4*)&As[alr][alc]   = av0;
        *(float4*)&As[alr][alc+4] = av1;
        *(float4*)&Ws[wlr][wlc]   = wv;
        __syncthreads();
        #pragma unroll
        for (int ks=0; ks<BK; ks+=8){
            unsigned a[2][4], b[4][2];
            #pragma unroll
            for (int mf=0;mf<2;mf++){
                int r = wm*32 + mf*16;
                a[mf][0]=f2tf(As[r+g  ][ks+tg  ]);
                a[mf][1]=f2tf(As[r+g+8][ks+tg  ]);
                a[mf][2]=f2tf(As[r+g  ][ks+tg+4]);
                a[mf][3]=f2tf(As[r+g+8][ks+tg+4]);
            }
            #pragma unroll
            for (int nf=0;nf<4;nf++){
                int n = wn*32 + nf*8;
                b[nf][0]=f2tf(Ws[n+g][ks+tg  ]);
                b[nf][1]=f2tf(Ws[n+g][ks+tg+4]);
            }
            #pragma unroll
            for (int mf=0;mf<2;mf++)
                #pragma unroll
                for (int nf=0;nf<4;nf++)
                    mma_tf32(c[mf][nf], a[mf], b[nf]);
        }
    }
    // epilogue
    #pragma unroll
    for (int mf=0;mf<2;mf++){
        #pragma unroll
        for (int nf=0;nf<4;nf++){
            int row = m0 + wm*32 + mf*16 + g;
            int col = n0 + wn*32 + nf*8 + 2*tg;
            #pragma unroll
            for (int hh=0; hh<2; hh++){
                int r = row + hh*8;
                float v0 = c[mf][nf][hh*2+0];
                float v1 = c[mf][nf][hh*2+1];
                if (MODE==0){
                    if (col < DI){
                        g_xssm[(size_t)r*DI + col]   = v0;
                        g_xssm[(size_t)r*DI + col+1] = v1;
                    } else {
                        g_z[(size_t)r*DI + col-DI]   = siluf(v0);
                        g_z[(size_t)r*DI + col-DI+1] = siluf(v1);
                    }
                } else if (MODE==1){
                    outp[(size_t)r*DM + col]   = v0;
                    outp[(size_t)r*DM + col+1] = v1;
                } else {
                    g_P[(size_t)r*(KD*CC) + col]   = v0;
                    g_P[(size_t)r*(KD*CC) + col+1] = v1;
                }
            }
        }
    }
}

// ---------------- conv1d depthwise (k=4, pad 1/2) + silu ----------------
__global__ __launch_bounds__(512) void conv_silu(const float* __restrict__ cw,
                                                 const float* __restrict__ cb){
    const int d  = threadIdx.x;
    const int b  = blockIdx.y;
    const int l0 = blockIdx.x * 64;
    const float w0=cw[d*4+0], w1=cw[d*4+1], w2=cw[d*4+2], w3=cw[d*4+3], bias=cb[d];
    const float* src = g_xssm + (size_t)b*Lseq*DI + d;
    float xm1 = (l0>0)   ? src[(size_t)(l0-1)*DI] : 0.f;
    float x0  =            src[(size_t)(l0  )*DI];
    float xp1 =            src[(size_t)(l0+1)*DI];
    #pragma unroll 4
    for (int l=l0; l<l0+64; l++){
        float xp2 = (l+2 < Lseq) ? src[(size_t)(l+2)*DI] : 0.f;
        float v = w0*xm1 + w1*x0 + w2*xp1 + w3*xp2 + bias;
        g_xcT[((size_t)b*Lseq + l)*DI + d] = siluf(v);
        xm1=x0; x0=xp1; xp1=xp2;
    }
}

// ---------------- scan helpers ----------------
__device__ __forceinline__ int lam_of(int l, int k){
    switch(k){
        case 0:  return l;
        case 1:  return Lseq-1-l;
        case 2:  return (l < Lseq/2) ? 2*l     : 2*(l-Lseq/2)+1;
        default: return (l < Lseq/2) ? 2*l + 1 : 2*(l-Lseq/2);
    }
}

__device__ __forceinline__ float softplusf(float x){
    float e0 = __expf(-fabsf(x));
    return fmaxf(x, 0.f) + __logf(1.f + e0);
}

// dA powers: pw[n] = e1^(n+1) via multiply tree
__device__ __forceinline__ void powchain(float e1, float (&pw)[16]){
    float e2 = e1*e1, e4 = e2*e2, e8 = e4*e4;
    pw[0]=e1;        pw[1]=e2;        pw[2]=e2*e1;     pw[3]=e4;
    pw[4]=e4*e1;     pw[5]=e4*e2;     pw[6]=pw[2]*e4;  pw[7]=e8;
    pw[8]=e8*e1;     pw[9]=e8*e2;     pw[10]=pw[2]*e8; pw[11]=e8*e4;
    pw[12]=pw[4]*e8; pw[13]=pw[5]*e8; pw[14]=pw[6]*e8; pw[15]=e8*e8;
}

__device__ __forceinline__ int check_chain(const float (&a)[16], float a0){
    int chain = 1;
    #pragma unroll
    for (int n=0;n<16;n++){
        float expect = a0 * (float)(n+1);
        if (fabsf(a[n]-expect) > 1e-4f*fabsf(expect) + 1e-30f) chain = 0;
    }
    return chain;
}

// ---------------- scan phase 1: per-chunk local scan -> h_out, S ----------------
template<bool CHAIN>
__device__ __forceinline__ void part1_loop(const float* sP, const float* su,
                                           const float (&dtw)[16], const float (&a)[16],
                                           float a0, float bias, float& S, float (&h)[16], int tid){
    for (int st = 0; st < LC; st++){
        const float* row = &sP[st*32];
        float x = bias;
        #pragma unroll
        for (int r=0;r<16;r++) x = fmaf(dtw[r], row[r], x);
        float delta = softplusf(x);
        S += delta;
        float du = delta * su[st*128 + tid];
        if (CHAIN){
            float pw[16]; powchain(__expf(delta*a0), pw);
            #pragma unroll
            for (int n=0;n<16;n++) h[n] = fmaf(h[n], pw[n], du * row[16+n]);
        } else {
            #pragma unroll
            for (int n=0;n<16;n++) h[n] = fmaf(h[n], __expf(delta*a[n]), du * row[16+n]);
        }
    }
}

__global__ __launch_bounds__(128) void scan_part1(const float* __restrict__ dt_proj_w,
                                                  const float* __restrict__ dt_bias,
                                                  const float* __restrict__ A_logs){
    const int tid = threadIdx.x;
    const int d   = blockIdx.x*128 + tid;
    const int ch  = blockIdx.y;
    const int bk  = blockIdx.z;          // b*4 + kd
    const int b   = bk >> 2, kd = bk & 3;

    float dtw[16], a[16];
    {
        const float4* p = (const float4*)&dt_proj_w[((size_t)kd*DI + d)*DR];
        #pragma unroll
        for (int q=0;q<4;q++){ float4 v=p[q]; dtw[4*q]=v.x; dtw[4*q+1]=v.y; dtw[4*q+2]=v.z; dtw[4*q+3]=v.w; }
        const float* al = &A_logs[((size_t)kd*DI + d)*DS];
        #pragma unroll
        for (int n=0;n<16;n++) a[n] = -__expf(al[n]);
    }
    const float a0 = a[0];
    const float bias = dt_bias[kd*DI + d];
    int chain = __syncthreads_and(check_chain(a, a0));

    __shared__ int   slam[LC];
    __shared__ float sP[LC*32];
    __shared__ float su[LC*128];
    if (tid < LC) slam[tid] = lam_of(ch*LC + tid, kd);
    __syncthreads();
    const float* Pb = g_P + (size_t)b*Lseq*(KD*CC) + kd*CC;
    const float* Ub = g_xcT + (size_t)b*Lseq*DI + blockIdx.x*128;
    for (int s = tid; s < LC*32; s += 128){
        int st = s >> 5, c = s & 31;
        sP[s] = Pb[(size_t)slam[st]*(KD*CC) + c];
    }
    for (int s = tid; s < LC*128; s += 128){
        int st = s >> 7, dd = s & 127;
        su[s] = Ub[(size_t)slam[st]*DI + dd];
    }
    __syncthreads();

    float h[16]; float S = 0.f;
    #pragma unroll
    for (int n=0;n<16;n++) h[n]=0.f;
    if (chain) part1_loop<true >(sP, su, dtw, a, a0, bias, S, h, tid);
    else       part1_loop<false>(sP, su, dtw, a, a0, bias, S, h, tid);

    size_t base = (((size_t)bk*NCH + ch)*DI + d);
    g_S[base] = S;
    #pragma unroll
    for (int n=0;n<16;n++) g_hout[base*DS + n] = h[n];
}

// ---------------- scan phase 2: compose chunk boundary states ----------------
__global__ __launch_bounds__(256) void scan_combine(const float* __restrict__ A_logs){
    int t = blockIdx.x*256 + threadIdx.x;      // (bk, d, n)
    int n  = t & 15;
    int d  = (t >> 4) & (DI-1);
    int bk = t >> 13;
    int kd = bk & 3;
    float a_n = -__expf(A_logs[((size_t)kd*DI + d)*DS + n]);
    float hin = 0.f;
    for (int c=0; c<NCH; c++){
        size_t base = (((size_t)bk*NCH + c)*DI + d);
        g_hin[base*DS + n] = hin;
        float S = g_S[base];
        hin = fmaf(hin, __expf(a_n*S), g_hout[base*DS + n]);
    }
}

// ---------------- scan phase 3: full per-chunk scan from hin, y + scatter ----------------
template<bool CHAIN>
__device__ __forceinline__ void part3_loop(const float* sP, const float* su, const int* slam,
                                           const float (&dtw)[16], const float (&a)[16],
                                           float a0, float bias, float Dd, float (&h)[16],
                                           float* __restrict__ Yb, int tid){
    for (int st = 0; st < LC; st++){
        const float* row = &sP[st*48];
        float x = bias;
        #pragma unroll
        for (int r=0;r<16;r++) x = fmaf(dtw[r], row[r], x);
        float delta = softplusf(x);
        float u  = su[st*128 + tid];
        float du = delta * u;
        float y = 0.f;
        if (CHAIN){
            float pw[16]; powchain(__expf(delta*a0), pw);
            #pragma unroll
            for (int n=0;n<16;n++){
                h[n] = fmaf(h[n], pw[n], du * row[16+n]);
                y = fmaf(h[n], row[32+n], y);
            }
        } else {
            #pragma unroll
            for (int n=0;n<16;n++){
                h[n] = fmaf(h[n], __expf(delta*a[n]), du * row[16+n]);
                y = fmaf(h[n], row[32+n], y);
            }
        }
        atomicAdd(&Yb[(size_t)slam[st]*DI], y + Dd*u);
    }
}

__global__ __launch_bounds__(128) void scan_part3(const float* __restrict__ dt_proj_w,
                                                  const float* __restrict__ dt_bias,
                                                  const float* __restrict__ A_logs,
                                                  const float* __restrict__ Ds){
    const int tid = threadIdx.x;
    const int d   = blockIdx.x*128 + tid;
    const int ch  = blockIdx.y;
    const int bk  = blockIdx.z;
    const int b   = bk >> 2, kd = bk & 3;

    float dtw[16], a[16];
    {
        const float4* p = (const float4*)&dt_proj_w[((size_t)kd*DI + d)*DR];
        #pragma unroll
        for (int q=0;q<4;q++){ float4 v=p[q]; dtw[4*q]=v.x; dtw[4*q+1]=v.y; dtw[4*q+2]=v.z; dtw[4*q+3]=v.w; }
        const float* al = &A_logs[((size_t)kd*DI + d)*DS];
        #pragma unroll
        for (int n=0;n<16;n++) a[n] = -__expf(al[n]);
    }
    const float a0 = a[0];
    const float bias = dt_bias[kd*DI + d];
    const float Dd   = Ds[kd*DI + d];
    int chain = __syncthreads_and(check_chain(a, a0));

    __shared__ int   slam[LC];
    __shared__ float sP[LC*48];
    __shared__ float su[LC*128];
    if (tid < LC) slam[tid] = lam_of(ch*LC + tid, kd);
    __syncthreads();
    const float* Pb = g_P + (size_t)b*Lseq*(KD*CC) + kd*CC;
    const float* Ub = g_xcT + (size_t)b*Lseq*DI + blockIdx.x*128;
    for (int s = tid; s < LC*48; s += 128){
        int st = s / 48, c = s - st*48;
        sP[s] = Pb[(size_t)slam[st]*(KD*CC) + c];
    }
    for (int s = tid; s < LC*128; s += 128){
        int st = s >> 7, dd = s & 127;
        su[s] = Ub[(size_t)slam[st]*DI + dd];
    }
    __syncthreads();

    float h[16];
    size_t base = (((size_t)bk*NCH + ch)*DI + d);
    #pragma unroll
    for (int n=0;n<16;n++) h[n] = g_hin[base*DS + n];

    float* Yb = g_ysum + (size_t)b*Lseq*DI + d;
    // Yb indexed as Yb[lam*DI] but d already folded: rebase without d
    Yb = g_ysum + (size_t)b*Lseq*DI + d;

    if (chain) part3_loop<true >(sP, su, slam, dtw, a, a0, bias, Dd, h, Yb, tid);
    else       part3_loop<false>(sP, su, slam, dtw, a, a0, bias, Dd, h, Yb, tid);
}

// ---------------- layernorm * ln_g + ln_b, gated by silu(z); in place ----------------
__global__ __launch_bounds__(128) void norm_kernel(const float* __restrict__ ln_g,
                                                   const float* __restrict__ ln_b){
    const int row = blockIdx.x;
    const int tid = threadIdx.x;
    float* y = g_ysum + (size_t)row*DI;
    const float* z = g_z + (size_t)row*DI;

    float4 v = ((const float4*)y)[tid];
    float s  = v.x+v.y+v.z+v.w;
    float sq = v.x*v.x + v.y*v.y + v.z*v.z + v.w*v.w;
    #pragma unroll
    for (int o=16;o>0;o>>=1){
        s  += __shfl_xor_sync(0xffffffffu, s,  o);
        sq += __shfl_xor_sync(0xffffffffu, sq, o);
    }
    __shared__ float ss[4], sqq[4];
    const int wid = tid >> 5, lane = tid & 31;
    if (lane==0){ ss[wid]=s; sqq[wid]=sq; }
    __syncthreads();
    s  = ss[0]+ss[1]+ss[2]+ss[3];
    sq = sqq[0]+sqq[1]+sqq[2]+sqq[3];
    const float mu  = s * (1.f/512.f);
    const float var = sq * (1.f/512.f) - mu*mu;
    const float rs  = rsqrtf(var + 1e-5f);

    float4 g4 = ((const float4*)ln_g)[tid];
    float4 b4 = ((const float4*)ln_b)[tid];
    float4 z4 = ((const float4*)z)[tid];
    v.x = ((v.x-mu)*rs*g4.x + b4.x) * z4.x;
    v.y = ((v.y-mu)*rs*g4.y + b4.y) * z4.y;
    v.z = ((v.z-mu)*rs*g4.z + b4.z) * z4.z;
    v.w = ((v.w-mu)*rs*g4.w + b4.w) * z4.w;
    ((float4*)y)[tid] = v;
}

// ---------------- launch ----------------
extern "C" void kernel_launch(void* const* d_in, const int* in_sizes, int n_in,
                              void* d_out, int out_size){
    const float* x          = (const float*)d_in[0];
    const float* in_proj_w  = (const float*)d_in[1];
    const float* conv_w     = (const float*)d_in[2];
    const float* conv_b     = (const float*)d_in[3];
    const float* x_proj_w   = (const float*)d_in[4];
    const float* dt_proj_w  = (const float*)d_in[5];
    const float* dt_bias    = (const float*)d_in[6];
    const float* A_logs     = (const float*)d_in[7];
    const float* Ds         = (const float*)d_in[8];
    const float* ln_g       = (const float*)d_in[9];
    const float* ln_b       = (const float*)d_in[10];
    const float* out_proj_w = (const float*)d_in[11];
    float* out = (float*)d_out;

    zero_ysum          <<<4096, 256>>>();
    gemm_tc<256,0>     <<<dim3(64,16), 256>>>(x, in_proj_w, nullptr);
    conv_silu          <<<dim3(16, 8), 512>>>(conv_w, conv_b);
    gemm_tc<512,2>     <<<dim3(64, 3), 256>>>(nullptr, x_proj_w, nullptr);
    scan_part1         <<<dim3(4, NCH, 32), 128>>>(dt_proj_w, dt_bias, A_logs);
    scan_combine       <<<1024, 256>>>(A_logs);
    scan_part3         <<<dim3(4, NCH, 32), 128>>>(dt_proj_w, dt_bias, A_logs, Ds);
    norm_kernel        <<<8192, 128>>>(ln_g, ln_b);
    gemm_tc<512,1>     <<<dim3(64, 4), 256>>>(nullptr, out_proj_w, out);
}

// round 4
// speedup vs baseline: 1.9273x; 1.0918x over previous
#include <cuda_runtime.h>
#include <cuda_bf16.h>

// ---------------- problem constants ----------------
constexpr int Bsz  = 8;
constexpr int Lseq = 1024;
constexpr int DM   = 256;   // d_model
constexpr int DI   = 512;   // d_inner
constexpr int DS   = 16;    // d_state
constexpr int DR   = 16;    // dt_rank
constexpr int KD   = 4;     // directions
constexpr int CC   = DR + 2*DS;  // 48
constexpr int NCH  = 16;    // scan chunks
constexpr int LC   = Lseq/NCH;   // 64 steps per chunk

// ---------------- scratch (device globals; no allocation) ----------------
__device__ float g_xssm[Bsz*Lseq*DI];
__device__ float g_z   [Bsz*Lseq*DI];
__device__ float g_xcT [Bsz*Lseq*DI];
__device__ float g_P   [Bsz*Lseq*KD*CC];
__device__ float g_ysum[Bsz*Lseq*DI];
__device__ float g_hout[Bsz*KD*NCH*DI*DS];
__device__ float g_hin [Bsz*KD*NCH*DI*DS];
__device__ float g_S   [Bsz*KD*NCH*DI];

__device__ __forceinline__ float siluf(float v){
    return v * (1.0f / (1.0f + __expf(-v)));
}
__device__ __forceinline__ unsigned f2tf(float f){
    unsigned u; asm("cvt.rna.tf32.f32 %0, %1;" : "=r"(u) : "f"(f)); return u;
}
__device__ __forceinline__ void mma_tf32(float (&c)[4], const unsigned (&a)[4], const unsigned (&b)[2]){
    asm volatile(
        "mma.sync.aligned.m16n8k8.row.col.f32.tf32.tf32.f32 "
        "{%0,%1,%2,%3}, {%4,%5,%6,%7}, {%8,%9}, {%0,%1,%2,%3};\n"
        : "+f"(c[0]), "+f"(c[1]), "+f"(c[2]), "+f"(c[3])
        : "r"(a[0]), "r"(a[1]), "r"(a[2]), "r"(a[3]), "r"(b[0]), "r"(b[1]));
}

// -------- packed f32x2 helpers --------
typedef unsigned long long ull;
__device__ __forceinline__ ull pk2(float lo, float hi){
    ull r; asm("mov.b64 %0, {%1,%2};" : "=l"(r) : "f"(lo), "f"(hi)); return r;
}
__device__ __forceinline__ void upk2(ull v, float& lo, float& hi){
    asm("mov.b64 {%0,%1}, %2;" : "=f"(lo), "=f"(hi) : "l"(v));
}
__device__ __forceinline__ ull fma2(ull a, ull b, ull c){
    ull d; asm("fma.rn.f32x2 %0, %1, %2, %3;" : "=l"(d) : "l"(a), "l"(b), "l"(c)); return d;
}
__device__ __forceinline__ ull mul2(ull a, ull b){
    ull d; asm("mul.rn.f32x2 %0, %1, %2;" : "=l"(d) : "l"(a), "l"(b)); return d;
}
__device__ __forceinline__ ull ld2(const float2 v){ return pk2(v.x, v.y); }

// ---------------- zero accumulator ----------------
__global__ void zero_ysum(){
    int i = blockIdx.x*blockDim.x + threadIdx.x;
    ((float4*)g_ysum)[i] = make_float4(0.f,0.f,0.f,0.f);
}

// ---------------- tf32 tensor-core GEMM, double-buffered: C = A @ W^T ----------------
// MODE 0: A=x (Mx256), W=in_proj_w (1024x256); split -> g_xssm / silu -> g_z
// MODE 1: A=g_ysum (Mx512), W=out_proj_w (256x512); write outp (Mx256)
// MODE 2: A=g_xcT (Mx512), W=x_proj_w as (192x512); write g_P (Mx192)
template<int KDIM, int MODE, int BN>
__global__ __launch_bounds__(256) void gemm_tc(const float* __restrict__ Ain,
                                               const float* __restrict__ W,
                                               float* __restrict__ outp){
    constexpr int BM=128, BK=16;
    constexpr int AP=BM+8, WP=BN+8;          // pad so k-rows offset by 8 banks
    constexpr int NF = BN/16;                // n-frags per warp (wn covers BN/2)
    __shared__ unsigned As[2][BK][AP];
    __shared__ unsigned Ws[2][BK][WP];
    const float* A = (MODE==0) ? Ain : (MODE==1 ? (const float*)g_ysum : (const float*)g_xcT);
    const int m0 = blockIdx.x*BM, n0 = blockIdx.y*BN;
    const int tid = threadIdx.x;
    const int wid = tid>>5, lane = tid&31;
    const int wm = wid & 3, wn = wid >> 2;   // 4 x 2 warps
    const int g = lane>>2, tg = lane&3;

    // global load mapping
    const int alr = tid>>1, alc = (tid&1)*8;                 // A: 128 x 16
    const int wlr = (BN==128) ? (tid>>1) : (tid>>2);         // W: BN x 16
    const int wlc = (BN==128) ? (tid&1)*8 : (tid&3)*4;
    constexpr int WREG = (BN==128) ? 8 : 4;

    const float* Ap = A + (size_t)(m0+alr)*KDIM + alc;
    const float* Wp = W + (size_t)(n0+wlr)*KDIM + wlc;

    float ar[8], wr[WREG];
    // initial load kt=0
    *(float4*)&ar[0] = *(const float4*)(Ap);
    *(float4*)&ar[4] = *(const float4*)(Ap+4);
    *(float4*)&wr[0] = *(const float4*)(Wp);
    if (WREG==8) *(float4*)&wr[4] = *(const float4*)(Wp+4);
    #pragma unroll
    for (int j=0;j<8;j++)    As[0][alc+j][alr] = f2tf(ar[j]);
    #pragma unroll
    for (int j=0;j<WREG;j++) Ws[0][wlc+j][wlr] = f2tf(wr[j]);
    __syncthreads();

    float c[2][NF][4] = {};
    int buf = 0;
    for (int kt = 0;;){
        const bool more = (kt + BK) < KDIM;
        if (more){
            *(float4*)&ar[0] = *(const float4*)(Ap + kt + BK);
            *(float4*)&ar[4] = *(const float4*)(Ap + kt + BK + 4);
            *(float4*)&wr[0] = *(const float4*)(Wp + kt + BK);
            if (WREG==8) *(float4*)&wr[4] = *(const float4*)(Wp + kt + BK + 4);
        }
        #pragma unroll
        for (int ks=0; ks<BK; ks+=8){
            unsigned a[2][4], b[NF][2];
            #pragma unroll
            for (int mf=0;mf<2;mf++){
                int r = wm*32 + mf*16;
                a[mf][0]=As[buf][ks+tg  ][r+g  ];
                a[mf][1]=As[buf][ks+tg  ][r+g+8];
                a[mf][2]=As[buf][ks+tg+4][r+g  ];
                a[mf][3]=As[buf][ks+tg+4][r+g+8];
            }
            #pragma unroll
            for (int nf=0;nf<NF;nf++){
                int n = wn*(BN/2) + nf*8;
                b[nf][0]=Ws[buf][ks+tg  ][n+g];
                b[nf][1]=Ws[buf][ks+tg+4][n+g];
            }
            #pragma unroll
            for (int mf=0;mf<2;mf++)
                #pragma unroll
                for (int nf=0;nf<NF;nf++)
                    mma_tf32(c[mf][nf], a[mf], b[nf]);
        }
        if (!more) break;
        #pragma unroll
        for (int j=0;j<8;j++)    As[buf^1][alc+j][alr] = f2tf(ar[j]);
        #pragma unroll
        for (int j=0;j<WREG;j++) Ws[buf^1][wlc+j][wlr] = f2tf(wr[j]);
        __syncthreads();
        buf ^= 1; kt += BK;
    }

    // epilogue
    #pragma unroll
    for (int mf=0;mf<2;mf++){
        #pragma unroll
        for (int nf=0;nf<NF;nf++){
            int row = m0 + wm*32 + mf*16 + g;
            int col = n0 + wn*(BN/2) + nf*8 + 2*tg;
            #pragma unroll
            for (int hh=0; hh<2; hh++){
                int r = row + hh*8;
                float v0 = c[mf][nf][hh*2+0];
                float v1 = c[mf][nf][hh*2+1];
                if (MODE==0){
                    if (col < DI){
                        g_xssm[(size_t)r*DI + col]   = v0;
                        g_xssm[(size_t)r*DI + col+1] = v1;
                    } else {
                        g_z[(size_t)r*DI + col-DI]   = siluf(v0);
                        g_z[(size_t)r*DI + col-DI+1] = siluf(v1);
                    }
                } else if (MODE==1){
                    outp[(size_t)r*DM + col]   = v0;
                    outp[(size_t)r*DM + col+1] = v1;
                } else {
                    g_P[(size_t)r*(KD*CC) + col]   = v0;
                    g_P[(size_t)r*(KD*CC) + col+1] = v1;
                }
            }
        }
    }
}

// ---------------- conv1d depthwise (k=4, pad 1/2) + silu ----------------
__global__ __launch_bounds__(512) void conv_silu(const float* __restrict__ cw,
                                                 const float* __restrict__ cb){
    const int d  = threadIdx.x;
    const int b  = blockIdx.y;
    const int l0 = blockIdx.x * 64;
    const float w0=cw[d*4+0], w1=cw[d*4+1], w2=cw[d*4+2], w3=cw[d*4+3], bias=cb[d];
    const float* src = g_xssm + (size_t)b*Lseq*DI + d;
    float xm1 = (l0>0)   ? src[(size_t)(l0-1)*DI] : 0.f;
    float x0  =            src[(size_t)(l0  )*DI];
    float xp1 =            src[(size_t)(l0+1)*DI];
    #pragma unroll 4
    for (int l=l0; l<l0+64; l++){
        float xp2 = (l+2 < Lseq) ? src[(size_t)(l+2)*DI] : 0.f;
        float v = w0*xm1 + w1*x0 + w2*xp1 + w3*xp2 + bias;
        g_xcT[((size_t)b*Lseq + l)*DI + d] = siluf(v);
        xm1=x0; x0=xp1; xp1=xp2;
    }
}

// ---------------- scan helpers ----------------
__device__ __forceinline__ int lam_of(int l, int k){
    switch(k){
        case 0:  return l;
        case 1:  return Lseq-1-l;
        case 2:  return (l < Lseq/2) ? 2*l     : 2*(l-Lseq/2)+1;
        default: return (l < Lseq/2) ? 2*l + 1 : 2*(l-Lseq/2);
    }
}
__device__ __forceinline__ float softplusf(float x){
    float e0 = __expf(-fabsf(x));
    return fmaxf(x, 0.f) + __logf(1.f + e0);
}
// packed powers: pw[j] = (e^(2j+1), e^(2j+2))
__device__ __forceinline__ void powchain2(float e1, ull (&pw)[8]){
    float e2=e1*e1, e4=e2*e2, e8=e4*e4;
    ull d2=pk2(e2,e2), d4=pk2(e4,e4), d8=pk2(e8,e8);
    pw[0]=pk2(e1,e2);
    pw[1]=mul2(pw[0],d2);
    pw[2]=mul2(pw[0],d4);
    pw[3]=mul2(pw[1],d4);
    pw[4]=mul2(pw[0],d8);
    pw[5]=mul2(pw[1],d8);
    pw[6]=mul2(pw[2],d8);
    pw[7]=mul2(pw[3],d8);
}
__device__ __forceinline__ void powchain(float e1, float (&pw)[16]){
    float e2 = e1*e1, e4 = e2*e2, e8 = e4*e4;
    pw[0]=e1;        pw[1]=e2;        pw[2]=e2*e1;     pw[3]=e4;
    pw[4]=e4*e1;     pw[5]=e4*e2;     pw[6]=pw[2]*e4;  pw[7]=e8;
    pw[8]=e8*e1;     pw[9]=e8*e2;     pw[10]=pw[2]*e8; pw[11]=e8*e4;
    pw[12]=pw[4]*e8; pw[13]=pw[5]*e8; pw[14]=pw[6]*e8; pw[15]=e8*e8;
}
__device__ __forceinline__ int check_chain(const float (&a)[16], float a0){
    int chain = 1;
    #pragma unroll
    for (int n=0;n<16;n++){
        float expect = a0 * (float)(n+1);
        if (fabsf(a[n]-expect) > 1e-4f*fabsf(expect) + 1e-30f) chain = 0;
    }
    return chain;
}

// ---------------- scan phase 1 ----------------
__device__ __forceinline__ void part1_chain(const float* sP, const float* su,
                                            const ull (&dtw2)[8], float a0, float bias,
                                            float& S, ull (&h2)[8], int tid){
    for (int st = 0; st < LC; st++){
        const float2* row2 = (const float2*)(sP + st*32);
        ull x2 = pk2(bias, 0.f);
        #pragma unroll
        for (int r=0;r<8;r++) x2 = fma2(dtw2[r], ld2(row2[r]), x2);
        float xl,xh; upk2(x2,xl,xh);
        float delta = softplusf(xl+xh);
        S += delta;
        ull pw[8]; powchain2(__expf(delta*a0), pw);
        float du = delta * su[st*128 + tid];
        ull du2 = pk2(du,du);
        #pragma unroll
        for (int j=0;j<8;j++)
            h2[j] = fma2(h2[j], pw[j], mul2(du2, ld2(row2[8+j])));
    }
}
__device__ __forceinline__ void part1_gen(const float* sP, const float* su,
                                          const float (&dtw)[16], const float (&a)[16],
                                          float bias, float& S, float (&h)[16], int tid){
    for (int st = 0; st < LC; st++){
        const float* row = &sP[st*32];
        float x = bias;
        #pragma unroll
        for (int r=0;r<16;r++) x = fmaf(dtw[r], row[r], x);
        float delta = softplusf(x);
        S += delta;
        float du = delta * su[st*128 + tid];
        #pragma unroll
        for (int n=0;n<16;n++) h[n] = fmaf(h[n], __expf(delta*a[n]), du * row[16+n]);
    }
}

__global__ __launch_bounds__(128) void scan_part1(const float* __restrict__ dt_proj_w,
                                                  const float* __restrict__ dt_bias,
                                                  const float* __restrict__ A_logs){
    const int tid = threadIdx.x;
    const int d   = blockIdx.x*128 + tid;
    const int ch  = blockIdx.y;
    const int bk  = blockIdx.z;
    const int b   = bk >> 2, kd = bk & 3;

    float dtw[16], a[16];
    {
        const float4* p = (const float4*)&dt_proj_w[((size_t)kd*DI + d)*DR];
        #pragma unroll
        for (int q=0;q<4;q++){ float4 v=p[q]; dtw[4*q]=v.x; dtw[4*q+1]=v.y; dtw[4*q+2]=v.z; dtw[4*q+3]=v.w; }
        const float* al = &A_logs[((size_t)kd*DI + d)*DS];
        #pragma unroll
        for (int n=0;n<16;n++) a[n] = -__expf(al[n]);
    }
    const float a0 = a[0];
    const float bias = dt_bias[kd*DI + d];
    int chain = __syncthreads_and(check_chain(a, a0));

    __shared__ int   slam[LC];
    __shared__ alignas(16) float sP[LC*32];
    __shared__ alignas(16) float su[LC*128];
    if (tid < LC) slam[tid] = lam_of(ch*LC + tid, kd);
    __syncthreads();
    const float* Pb = g_P + (size_t)b*Lseq*(KD*CC) + kd*CC;
    const float* Ub = g_xcT + (size_t)b*Lseq*DI + blockIdx.x*128;
    for (int s = tid; s < LC*32; s += 128){
        int st = s >> 5, c = s & 31;
        sP[s] = Pb[(size_t)slam[st]*(KD*CC) + c];
    }
    for (int s = tid; s < LC*128; s += 128){
        int st = s >> 7, dd = s & 127;
        su[s] = Ub[(size_t)slam[st]*DI + dd];
    }
    __syncthreads();

    size_t base = (((size_t)bk*NCH + ch)*DI + d);
    float S = 0.f;
    if (chain){
        ull dtw2[8], h2[8];
        #pragma unroll
        for (int j=0;j<8;j++){ dtw2[j]=pk2(dtw[2*j],dtw[2*j+1]); h2[j]=0ull; }
        part1_chain(sP, su, dtw2, a0, bias, S, h2, tid);
        #pragma unroll
        for (int j=0;j<8;j++){
            float lo,hi; upk2(h2[j],lo,hi);
            g_hout[base*DS + 2*j]   = lo;
            g_hout[base*DS + 2*j+1] = hi;
        }
    } else {
        float h[16];
        #pragma unroll
        for (int n=0;n<16;n++) h[n]=0.f;
        part1_gen(sP, su, dtw, a, bias, S, h, tid);
        #pragma unroll
        for (int n=0;n<16;n++) g_hout[base*DS + n] = h[n];
    }
    g_S[base] = S;
}

// ---------------- scan phase 2: compose chunk boundary states ----------------
__global__ __launch_bounds__(256) void scan_combine(const float* __restrict__ A_logs){
    int t = blockIdx.x*256 + threadIdx.x;
    int n  = t & 15;
    int d  = (t >> 4) & (DI-1);
    int bk = t >> 13;
    int kd = bk & 3;
    float a_n = -__expf(A_logs[((size_t)kd*DI + d)*DS + n]);
    float hin = 0.f;
    for (int c=0; c<NCH; c++){
        size_t base = (((size_t)bk*NCH + c)*DI + d);
        g_hin[base*DS + n] = hin;
        float S = g_S[base];
        hin = fmaf(hin, __expf(a_n*S), g_hout[base*DS + n]);
    }
}

// ---------------- scan phase 3 ----------------
__device__ __forceinline__ void part3_chain(const float* sP, const float* su, const int* slam,
                                            const ull (&dtw2)[8], float a0, float bias, float Dd,
                                            ull (&h2)[8], float* __restrict__ Yb, int tid){
    for (int st = 0; st < LC; st++){
        const float2* row2 = (const float2*)(sP + st*48);
        ull x2 = pk2(bias, 0.f);
        #pragma unroll
        for (int r=0;r<8;r++) x2 = fma2(dtw2[r], ld2(row2[r]), x2);
        float xl,xh; upk2(x2,xl,xh);
        float delta = softplusf(xl+xh);
        ull pw[8]; powchain2(__expf(delta*a0), pw);
        float u  = su[st*128 + tid];
        float du = delta * u;
        ull du2 = pk2(du,du);
        ull y2 = 0ull;
        #pragma unroll
        for (int j=0;j<8;j++){
            h2[j] = fma2(h2[j], pw[j], mul2(du2, ld2(row2[8+j])));
            y2 = fma2(h2[j], ld2(row2[16+j]), y2);
        }
        float yl,yh; upk2(y2,yl,yh);
        atomicAdd(&Yb[(size_t)slam[st]*DI], yl + yh + Dd*u);
    }
}
__device__ __forceinline__ void part3_gen(const float* sP, const float* su, const int* slam,
                                          const float (&dtw)[16], const float (&a)[16],
                                          float bias, float Dd, float (&h)[16],
                                          float* __restrict__ Yb, int tid){
    for (int st = 0; st < LC; st++){
        const float* row = &sP[st*48];
        float x = bias;
        #pragma unroll
        for (int r=0;r<16;r++) x = fmaf(dtw[r], row[r], x);
        float delta = softplusf(x);
        float u  = su[st*128 + tid];
        float du = delta * u;
        float y = 0.f;
        #pragma unroll
        for (int n=0;n<16;n++){
            h[n] = fmaf(h[n], __expf(delta*a[n]), du * row[16+n]);
            y = fmaf(h[n], row[32+n], y);
        }
        atomicAdd(&Yb[(size_t)slam[st]*DI], y + Dd*u);
    }
}

__global__ __launch_bounds__(128) void scan_part3(const float* __restrict__ dt_proj_w,
                                                  const float* __restrict__ dt_bias,
                                                  const float* __restrict__ A_logs,
                                                  const float* __restrict__ Ds){
    const int tid = threadIdx.x;
    const int d   = blockIdx.x*128 + tid;
    const int ch  = blockIdx.y;
    const int bk  = blockIdx.z;
    const int b   = bk >> 2, kd = bk & 3;

    float dtw[16], a[16];
    {
        const float4* p = (const float4*)&dt_proj_w[((size_t)kd*DI + d)*DR];
        #pragma unroll
        for (int q=0;q<4;q++){ float4 v=p[q]; dtw[4*q]=v.x; dtw[4*q+1]=v.y; dtw[4*q+2]=v.z; dtw[4*q+3]=v.w; }
        const float* al = &A_logs[((size_t)kd*DI + d)*DS];
        #pragma unroll
        for (int n=0;n<16;n++) a[n] = -__expf(al[n]);
    }
    const float a0 = a[0];
    const float bias = dt_bias[kd*DI + d];
    const float Dd   = Ds[kd*DI + d];
    int chain = __syncthreads_and(check_chain(a, a0));

    __shared__ int   slam[LC];
    __shared__ alignas(16) float sP[LC*48];
    __shared__ alignas(16) float su[LC*128];
    if (tid < LC) slam[tid] = lam_of(ch*LC + tid, kd);
    __syncthreads();
    const float* Pb = g_P + (size_t)b*Lseq*(KD*CC) + kd*CC;
    const float* Ub = g_xcT + (size_t)b*Lseq*DI + blockIdx.x*128;
    for (int s = tid; s < LC*48; s += 128){
        int st = s / 48, c = s - st*48;
        sP[s] = Pb[(size_t)slam[st]*(KD*CC) + c];
    }
    for (int s = tid; s < LC*128; s += 128){
        int st = s >> 7, dd = s & 127;
        su[s] = Ub[(size_t)slam[st]*DI + dd];
    }
    __syncthreads();

    size_t base = (((size_t)bk*NCH + ch)*DI + d);
    float* Yb = g_ysum + (size_t)b*Lseq*DI + d;

    if (chain){
        ull dtw2[8], h2[8];
        #pragma unroll
        for (int j=0;j<8;j++){
            dtw2[j]=pk2(dtw[2*j],dtw[2*j+1]);
            h2[j]=pk2(g_hin[base*DS + 2*j], g_hin[base*DS + 2*j+1]);
        }
        part3_chain(sP, su, slam, dtw2, a0, bias, Dd, h2, Yb, tid);
    } else {
        float h[16];
        #pragma unroll
        for (int n=0;n<16;n++) h[n] = g_hin[base*DS + n];
        part3_gen(sP, su, slam, dtw, a, bias, Dd, h, Yb, tid);
    }
}

// ---------------- layernorm * ln_g + ln_b, gated by silu(z); in place ----------------
__global__ __launch_bounds__(128) void norm_kernel(const float* __restrict__ ln_g,
                                                   const float* __restrict__ ln_b){
    const int row = blockIdx.x;
    const int tid = threadIdx.x;
    float* y = g_ysum + (size_t)row*DI;
    const float* z = g_z + (size_t)row*DI;

    float4 v = ((const float4*)y)[tid];
    float s  = v.x+v.y+v.z+v.w;
    float sq = v.x*v.x + v.y*v.y + v.z*v.z + v.w*v.w;
    #pragma unroll
    for (int o=16;o>0;o>>=1){
        s  += __shfl_xor_sync(0xffffffffu, s,  o);
        sq += __shfl_xor_sync(0xffffffffu, sq, o);
    }
    __shared__ float ss[4], sqq[4];
    const int wid = tid >> 5, lane = tid & 31;
    if (lane==0){ ss[wid]=s; sqq[wid]=sq; }
    __syncthreads();
    s  = ss[0]+ss[1]+ss[2]+ss[3];
    sq = sqq[0]+sqq[1]+sqq[2]+sqq[3];
    const float mu  = s * (1.f/512.f);
    const float var = sq * (1.f/512.f) - mu*mu;
    const float rs  = rsqrtf(var + 1e-5f);

    float4 g4 = ((const float4*)ln_g)[tid];
    float4 b4 = ((const float4*)ln_b)[tid];
    float4 z4 = ((const float4*)z)[tid];
    v.x = ((v.x-mu)*rs*g4.x + b4.x) * z4.x;
    v.y = ((v.y-mu)*rs*g4.y + b4.y) * z4.y;
    v.z = ((v.z-mu)*rs*g4.z + b4.z) * z4.z;
    v.w = ((v.w-mu)*rs*g4.w + b4.w) * z4.w;
    ((float4*)y)[tid] = v;
}

// ---------------- launch ----------------
extern "C" void kernel_launch(void* const* d_in, const int* in_sizes, int n_in,
                              void* d_out, int out_size){
    const float* x          = (const float*)d_in[0];
    const float* in_proj_w  = (const float*)d_in[1];
    const float* conv_w     = (const float*)d_in[2];
    const float* conv_b     = (const float*)d_in[3];
    const float* x_proj_w   = (const float*)d_in[4];
    const float* dt_proj_w  = (const float*)d_in[5];
    const float* dt_bias    = (const float*)d_in[6];
    const float* A_logs     = (const float*)d_in[7];
    const float* Ds         = (const float*)d_in[8];
    const float* ln_g       = (const float*)d_in[9];
    const float* ln_b       = (const float*)d_in[10];
    const float* out_proj_w = (const float*)d_in[11];
    float* out = (float*)d_out;

    zero_ysum            <<<4096, 256>>>();
    gemm_tc<256,0,128>   <<<dim3(64, 8), 256>>>(x, in_proj_w, nullptr);
    conv_silu            <<<dim3(16, 8), 512>>>(conv_w, conv_b);
    gemm_tc<512,2, 64>   <<<dim3(64, 3), 256>>>(nullptr, x_proj_w, nullptr);
    scan_part1           <<<dim3(4, NCH, 32), 128>>>(dt_proj_w, dt_bias, A_logs);
    scan_combine         <<<1024, 256>>>(A_logs);
    scan_part3           <<<dim3(4, NCH, 32), 128>>>(dt_proj_w, dt_bias, A_logs, Ds);
    norm_kernel          <<<8192, 128>>>(ln_g, ln_b);
    gemm_tc<512,1,128>   <<<dim3(64, 2), 256>>>(nullptr, out_proj_w, out);
}